// round 14
// baseline (speedup 1.0000x reference)
#include <cuda_runtime.h>
#include <stdint.h>

// FINAL (converged; re-benched 5x: 84.0-84.7 us, DRAM 87.2-88.9%).
// out_flat[4p+k] = X_flat[40p+10k+9] / X_flat[40p+10k] - 2,  k=0..3
// (row stride 4000 = 100 periods of 40 -> flat processing is exact)
//
// Evidence-backed design (R1-R13):
//  - dense, memcpy-identical LDG.128 load stream (every byte consumed;
//    sparse/strided alternatives inflated L1/L2 traffic or request count)
//  - warp-local SMEM gather, __syncwarp only (block barriers chopped the
//    DRAM request stream -16%; shuffle repack evaluated: L1/issue not
//    binding, predicted delta 0; cp.async below its N>=32 break-even)
//  - non-persistent grid: CTA churn supplies chip-level load pipelining
//    (persistent and software-pipelined persistent variants both -5%)
//  - 64-thread CTAs: churn-granularity optimum; 64 warps/SM = HW cap
// Traffic is sector-irreducible (all 5 sectors/period carry needed data):
// 564 MB at ~7.0 TB/s (the measured mixed-stream ceiling, path-independent
// across LDG/hints/layouts) = 80-81 us; ncu dur 81.1-82.6 us (within 1.5%).

static constexpr long long N_FLOATS = 64LL * 512 * 4000;        // 131,072,000
static constexpr int TILE_F4   = 160;                            // float4 per warp-tile (640 floats)
static constexpr int TILE_OUT  = 64;                             // outputs per warp-tile
static constexpr int WARPS_PER_BLK = 2;
static constexpr int THREADS   = WARPS_PER_BLK * 32;             // 64
static constexpr long long N_TILES = N_FLOATS / (TILE_F4 * 4);   // 204,800
static constexpr int N_BLOCKS = (int)(N_TILES / WARPS_PER_BLK);  // 102,400

__global__ __launch_bounds__(THREADS) void ts_return_kernel(
    const float4* __restrict__ X4, float* __restrict__ out)
{
    __shared__ float s[WARPS_PER_BLK][TILE_F4 * 4];   // 640 floats / warp

    const uint32_t w = threadIdx.x >> 5;
    const uint32_t l = threadIdx.x & 31;
    const uint32_t tile = blockIdx.x * WARPS_PER_BLK + w;

    const float4* __restrict__ p = X4 + (size_t)tile * TILE_F4;

    // 5 independent, fully coalesced 128B-per-warp loads (dense stream).
    float4 v0 = p[l];
    float4 v1 = p[32 + l];
    float4 v2 = p[64 + l];
    float4 v3 = p[96 + l];
    float4 v4 = p[128 + l];

    float4* __restrict__ sv = (float4*)s[w];
    sv[l]        = v0;
    sv[32 + l]   = v1;
    sv[64 + l]   = v2;
    sv[96 + l]   = v3;
    sv[128 + l]  = v4;
    __syncwarp();

    // Gather: output o (0..63) needs s[10o] and s[10o+9].
    const float* __restrict__ sw = s[w];
    uint32_t i0 = 10u * l;          // o = l
    uint32_t i1 = i0 + 320u;        // o = l + 32
    float r0 = __fdividef(sw[i0 + 9], sw[i0]) - 2.0f;
    float r1 = __fdividef(sw[i1 + 9], sw[i1]) - 2.0f;

    float* __restrict__ d = out + (size_t)tile * TILE_OUT;
    d[l]      = r0;    // coalesced 128B
    d[32 + l] = r1;    // coalesced 128B
}

extern "C" void kernel_launch(void* const* d_in, const int* in_sizes, int n_in,
                              void* d_out, int out_size)
{
    const float4* X4 = (const float4*)d_in[0];
    float* out = (float*)d_out;
    ts_return_kernel<<<N_BLOCKS, THREADS>>>(X4, out);
}

// round 15
// speedup vs baseline: 1.0084x; 1.0084x over previous
#include <cuda_runtime.h>
#include <stdint.h>

// FINAL (converged; re-benched 6x: 84.0-84.7 us, DRAM 87.2-88.9%).
// out_flat[4p+k] = X_flat[40p+10k+9] / X_flat[40p+10k] - 2,  k=0..3
// (row stride 4000 = 100 periods of 40 -> flat processing is exact)
//
// Evidence-backed design (R1-R14):
//  - dense, memcpy-identical LDG.128 load stream (every byte consumed;
//    sparse/strided alternatives inflated L1/L2 traffic or request count)
//  - warp-local SMEM gather, __syncwarp only (block barriers chopped the
//    DRAM request stream -16%; shuffle repack: L1/issue not binding,
//    predicted delta 0; cp.async below its N>=32 break-even at N=5)
//  - non-persistent grid: CTA churn supplies chip-level load pipelining
//    (persistent and software-pipelined persistent variants both -5%)
//  - 64-thread CTAs: churn-granularity optimum (256->128 helped, 128->64
//    flat; 32 would halve threads/SM at the 32-CTA residency cap)
// Traffic is sector-irreducible (all 5 sectors/period carry needed data):
// 564 MB at ~7.0 TB/s (the measured mixed-stream ceiling, path-independent
// across LDG/hints/layouts) = 80-81 us; ncu dur 81.1-82.6 us (within 1.5%).

static constexpr long long N_FLOATS = 64LL * 512 * 4000;        // 131,072,000
static constexpr int TILE_F4   = 160;                            // float4 per warp-tile (640 floats)
static constexpr int TILE_OUT  = 64;                             // outputs per warp-tile
static constexpr int WARPS_PER_BLK = 2;
static constexpr int THREADS   = WARPS_PER_BLK * 32;             // 64
static constexpr long long N_TILES = N_FLOATS / (TILE_F4 * 4);   // 204,800
static constexpr int N_BLOCKS = (int)(N_TILES / WARPS_PER_BLK);  // 102,400

__global__ __launch_bounds__(THREADS) void ts_return_kernel(
    const float4* __restrict__ X4, float* __restrict__ out)
{
    __shared__ float s[WARPS_PER_BLK][TILE_F4 * 4];   // 640 floats / warp

    const uint32_t w = threadIdx.x >> 5;
    const uint32_t l = threadIdx.x & 31;
    const uint32_t tile = blockIdx.x * WARPS_PER_BLK + w;

    const float4* __restrict__ p = X4 + (size_t)tile * TILE_F4;

    // 5 independent, fully coalesced 128B-per-warp loads (dense stream).
    float4 v0 = p[l];
    float4 v1 = p[32 + l];
    float4 v2 = p[64 + l];
    float4 v3 = p[96 + l];
    float4 v4 = p[128 + l];

    float4* __restrict__ sv = (float4*)s[w];
    sv[l]        = v0;
    sv[32 + l]   = v1;
    sv[64 + l]   = v2;
    sv[96 + l]   = v3;
    sv[128 + l]  = v4;
    __syncwarp();

    // Gather: output o (0..63) needs s[10o] and s[10o+9].
    const float* __restrict__ sw = s[w];
    uint32_t i0 = 10u * l;          // o = l
    uint32_t i1 = i0 + 320u;        // o = l + 32
    float r0 = __fdividef(sw[i0 + 9], sw[i0]) - 2.0f;
    float r1 = __fdividef(sw[i1 + 9], sw[i1]) - 2.0f;

    float* __restrict__ d = out + (size_t)tile * TILE_OUT;
    d[l]      = r0;    // coalesced 128B
    d[32 + l] = r1;    // coalesced 128B
}

extern "C" void kernel_launch(void* const* d_in, const int* in_sizes, int n_in,
                              void* d_out, int out_size)
{
    const float4* X4 = (const float4*)d_in[0];
    float* out = (float*)d_out;
    ts_return_kernel<<<N_BLOCKS, THREADS>>>(X4, out);
}